// round 1
// baseline (speedup 1.0000x reference)
#include <cuda_runtime.h>
#include <math.h>

// Problem constants
#define BATCH 8
#define SEQ   2048
#define DIM   512           // D == DIM_ATTN == DIM_VAL == 512
#define MTOT  (BATCH*SEQ)   // 16384

// Device scratch (allocation-free rule: __device__ globals)
__device__ float g_Q[BATCH * SEQ * DIM];
__device__ float g_K[BATCH * SEQ * DIM];
__device__ float g_V[BATCH * SEQ * DIM];
__device__ float g_S[(size_t)BATCH * SEQ * SEQ];   // 134 MB scores

// ---------------------------------------------------------------------------
// Canonical 128x128x8 fp32 SGEMM, NN layout: C[M,N] = A[M,K] * B[K,N]
// Optional bias + relu epilogue. Batched via per-z strides.
// 256 threads, each computes an 8x8 micro-tile.
// ---------------------------------------------------------------------------
__global__ __launch_bounds__(256)
void sgemm_nn(const float* __restrict__ A, const float* __restrict__ Bm,
              const float* __restrict__ bias, float* __restrict__ C,
              int M, int N, int K,
              size_t sA, size_t sB, size_t sC, int relu)
{
    __shared__ float As[8][128];
    __shared__ float Bs[8][128];

    const int z = blockIdx.z;
    A  += (size_t)z * sA;
    Bm += (size_t)z * sB;
    C  += (size_t)z * sC;

    const int rowBase = blockIdx.y * 128;
    const int colBase = blockIdx.x * 128;
    const int t  = threadIdx.x;
    const int tx = t & 15;
    const int ty = t >> 4;

    // A-tile load mapping: 128 rows x 8 cols, one float4 per thread
    const int aRow = t >> 1;
    const int aCol = (t & 1) << 2;
    // B-tile load mapping: 8 rows x 128 cols, one float4 per thread
    const int bRow = t >> 5;
    const int bCol = (t & 31) << 2;

    float acc[8][8];
    #pragma unroll
    for (int i = 0; i < 8; i++)
        #pragma unroll
        for (int j = 0; j < 8; j++) acc[i][j] = 0.0f;

    for (int k0 = 0; k0 < K; k0 += 8) {
        float4 a4 = *(const float4*)&A[(size_t)(rowBase + aRow) * K + k0 + aCol];
        As[aCol + 0][aRow] = a4.x;
        As[aCol + 1][aRow] = a4.y;
        As[aCol + 2][aRow] = a4.z;
        As[aCol + 3][aRow] = a4.w;

        float4 b4 = *(const float4*)&Bm[(size_t)(k0 + bRow) * N + colBase + bCol];
        *(float4*)&Bs[bRow][bCol] = b4;

        __syncthreads();

        #pragma unroll
        for (int kk = 0; kk < 8; kk++) {
            float ra[8], rb[8];
            #pragma unroll
            for (int i = 0; i < 8; i++) ra[i] = As[kk][ty * 8 + i];
            #pragma unroll
            for (int j = 0; j < 8; j++) rb[j] = Bs[kk][tx * 8 + j];
            #pragma unroll
            for (int i = 0; i < 8; i++)
                #pragma unroll
                for (int j = 0; j < 8; j++)
                    acc[i][j] = fmaf(ra[i], rb[j], acc[i][j]);
        }
        __syncthreads();
    }

    #pragma unroll
    for (int i = 0; i < 8; i++) {
        const int r = rowBase + ty * 8 + i;
        #pragma unroll
        for (int j = 0; j < 8; j += 4) {
            const int c = colBase + tx * 8 + j;
            float4 v;
            v.x = acc[i][j + 0];
            v.y = acc[i][j + 1];
            v.z = acc[i][j + 2];
            v.w = acc[i][j + 3];
            if (bias) {
                v.x += bias[c + 0]; v.y += bias[c + 1];
                v.z += bias[c + 2]; v.w += bias[c + 3];
            }
            if (relu) {
                v.x = fmaxf(v.x, 0.0f); v.y = fmaxf(v.y, 0.0f);
                v.z = fmaxf(v.z, 0.0f); v.w = fmaxf(v.w, 0.0f);
            }
            *(float4*)&C[(size_t)r * N + c] = v;
        }
    }
}

// ---------------------------------------------------------------------------
// NT SGEMM: C[M,N] = scale * A[M,K] * B[N,K]^T   (scores = scale * Q K^T)
// Both A and B are row-major [rows, K]. Batched via z strides.
// ---------------------------------------------------------------------------
__global__ __launch_bounds__(256)
void sgemm_nt(const float* __restrict__ A, const float* __restrict__ Bm,
              float* __restrict__ C,
              int M, int N, int K,
              size_t sA, size_t sB, size_t sC, float scale)
{
    __shared__ float As[8][128];
    __shared__ float Bs[8][128];

    const int z = blockIdx.z;
    A  += (size_t)z * sA;
    Bm += (size_t)z * sB;
    C  += (size_t)z * sC;

    const int rowBase = blockIdx.y * 128;
    const int colBase = blockIdx.x * 128;
    const int t  = threadIdx.x;
    const int tx = t & 15;
    const int ty = t >> 4;

    const int aRow = t >> 1;
    const int aCol = (t & 1) << 2;

    float acc[8][8];
    #pragma unroll
    for (int i = 0; i < 8; i++)
        #pragma unroll
        for (int j = 0; j < 8; j++) acc[i][j] = 0.0f;

    for (int k0 = 0; k0 < K; k0 += 8) {
        float4 a4 = *(const float4*)&A[(size_t)(rowBase + aRow) * K + k0 + aCol];
        As[aCol + 0][aRow] = a4.x;
        As[aCol + 1][aRow] = a4.y;
        As[aCol + 2][aRow] = a4.z;
        As[aCol + 3][aRow] = a4.w;

        // B rows indexed by output column n; contiguous along K
        float4 b4 = *(const float4*)&Bm[(size_t)(colBase + aRow) * K + k0 + aCol];
        Bs[aCol + 0][aRow] = b4.x;
        Bs[aCol + 1][aRow] = b4.y;
        Bs[aCol + 2][aRow] = b4.z;
        Bs[aCol + 3][aRow] = b4.w;

        __syncthreads();

        #pragma unroll
        for (int kk = 0; kk < 8; kk++) {
            float ra[8], rb[8];
            #pragma unroll
            for (int i = 0; i < 8; i++) ra[i] = As[kk][ty * 8 + i];
            #pragma unroll
            for (int j = 0; j < 8; j++) rb[j] = Bs[kk][tx * 8 + j];
            #pragma unroll
            for (int i = 0; i < 8; i++)
                #pragma unroll
                for (int j = 0; j < 8; j++)
                    acc[i][j] = fmaf(ra[i], rb[j], acc[i][j]);
        }
        __syncthreads();
    }

    #pragma unroll
    for (int i = 0; i < 8; i++) {
        const int r = rowBase + ty * 8 + i;
        #pragma unroll
        for (int j = 0; j < 8; j += 4) {
            const int c = colBase + tx * 8 + j;
            float4 v;
            v.x = acc[i][j + 0] * scale;
            v.y = acc[i][j + 1] * scale;
            v.z = acc[i][j + 2] * scale;
            v.w = acc[i][j + 3] * scale;
            *(float4*)&C[(size_t)r * N + c] = v;
        }
    }
}

// ---------------------------------------------------------------------------
// Row softmax over 2048 columns, one block (256 threads) per row, in-place.
// ---------------------------------------------------------------------------
__global__ __launch_bounds__(256)
void softmax_rows(float* __restrict__ S)
{
    float* row = S + (size_t)blockIdx.x * SEQ;
    const int t = threadIdx.x;
    __shared__ float red[256];

    float vals[8];
    float vmax = -INFINITY;
    #pragma unroll
    for (int i = 0; i < 8; i++) {
        vals[i] = row[t + i * 256];
        vmax = fmaxf(vmax, vals[i]);
    }

    red[t] = vmax;
    __syncthreads();
    #pragma unroll
    for (int s = 128; s > 0; s >>= 1) {
        if (t < s) red[t] = fmaxf(red[t], red[t + s]);
        __syncthreads();
    }
    const float m = red[0];
    __syncthreads();

    float sum = 0.0f;
    #pragma unroll
    for (int i = 0; i < 8; i++) {
        vals[i] = expf(vals[i] - m);
        sum += vals[i];
    }
    red[t] = sum;
    __syncthreads();
    #pragma unroll
    for (int s = 128; s > 0; s >>= 1) {
        if (t < s) red[t] += red[t + s];
        __syncthreads();
    }
    const float inv = 1.0f / red[0];

    #pragma unroll
    for (int i = 0; i < 8; i++)
        row[t + i * 256] = vals[i] * inv;
}

// ---------------------------------------------------------------------------
extern "C" void kernel_launch(void* const* d_in, const int* in_sizes, int n_in,
                              void* d_out, int out_size)
{
    const float* x  = (const float*)d_in[0];
    const float* Wq = (const float*)d_in[1];
    const float* bq = (const float*)d_in[2];
    const float* Wk = (const float*)d_in[3];
    const float* bk = (const float*)d_in[4];
    const float* Wv = (const float*)d_in[5];
    const float* bv = (const float*)d_in[6];
    float* out = (float*)d_out;

    float *Q, *K, *V, *S;
    cudaGetSymbolAddress((void**)&Q, g_Q);
    cudaGetSymbolAddress((void**)&K, g_K);
    cudaGetSymbolAddress((void**)&V, g_V);
    cudaGetSymbolAddress((void**)&S, g_S);

    // 1) QKV projections + bias + relu:  [16384,512] x [512,512]
    {
        dim3 grid(DIM / 128, MTOT / 128, 1);
        sgemm_nn<<<grid, 256>>>(x, Wq, bq, Q, MTOT, DIM, DIM, 0, 0, 0, 1);
        sgemm_nn<<<grid, 256>>>(x, Wk, bk, K, MTOT, DIM, DIM, 0, 0, 0, 1);
        sgemm_nn<<<grid, 256>>>(x, Wv, bv, V, MTOT, DIM, DIM, 0, 0, 0, 1);
    }

    // 2) scores = scale * Q K^T per batch:  [2048,512] x [2048,512]^T
    {
        const float scale = 1.0f / sqrtf((float)DIM);
        dim3 grid(SEQ / 128, SEQ / 128, BATCH);
        sgemm_nt<<<grid, 256>>>(Q, K, S, SEQ, SEQ, DIM,
                                (size_t)SEQ * DIM, (size_t)SEQ * DIM,
                                (size_t)SEQ * SEQ, scale);
    }

    // 3) softmax over rows of scores
    softmax_rows<<<BATCH * SEQ, 256>>>(S);

    // 4) out = attn * V per batch:  [2048,2048] x [2048,512]
    {
        dim3 grid(DIM / 128, SEQ / 128, BATCH);
        sgemm_nn<<<grid, 256>>>(S, V, nullptr, out, SEQ, DIM, SEQ,
                                (size_t)SEQ * SEQ, (size_t)SEQ * DIM,
                                (size_t)SEQ * DIM, 0);
    }
}

// round 3
// speedup vs baseline: 2.3639x; 2.3639x over previous
#include <cuda_runtime.h>
#include <cuda_bf16.h>
#include <math.h>
#include <stdint.h>

#define BATCH 8
#define SEQ   2048
#define DIM   512
#define MTOT  (BATCH*SEQ)   // 16384

// ---------------------------------------------------------------------------
// Device scratch (allocation-free rule: __device__ globals)
// ---------------------------------------------------------------------------
__device__ __nv_bfloat16 g_xh[MTOT * DIM], g_xl[MTOT * DIM];
__device__ __nv_bfloat16 g_Wqt_h[DIM * DIM], g_Wqt_l[DIM * DIM];
__device__ __nv_bfloat16 g_Wkt_h[DIM * DIM], g_Wkt_l[DIM * DIM];
__device__ __nv_bfloat16 g_Wvt_h[DIM * DIM], g_Wvt_l[DIM * DIM];
__device__ __nv_bfloat16 g_Qh[MTOT * DIM], g_Ql[MTOT * DIM];
__device__ __nv_bfloat16 g_Kh[MTOT * DIM], g_Kl[MTOT * DIM];
__device__ float         g_V[MTOT * DIM];
__device__ __nv_bfloat16 g_Vth[MTOT * DIM], g_Vtl[MTOT * DIM];  // [B][DIM][SEQ]
__device__ float         g_S [(size_t)BATCH * SEQ * SEQ];
__device__ __nv_bfloat16 g_Ph[(size_t)BATCH * SEQ * SEQ];
__device__ __nv_bfloat16 g_Pl[(size_t)BATCH * SEQ * SEQ];

// ---------------------------------------------------------------------------
// Baseline-ISA helpers: ldmatrix / mma.sync / cp.async  (no 'a' features)
// ---------------------------------------------------------------------------
__device__ __forceinline__ uint32_t smem_to_u32(const void* p) {
    uint32_t a;
    asm("{ .reg .u64 t; cvta.to.shared.u64 t, %1; cvt.u32.u64 %0, t; }" : "=r"(a) : "l"(p));
    return a;
}
__device__ __forceinline__ void ldsm4(uint32_t* r, uint32_t addr) {
    asm volatile("ldmatrix.sync.aligned.m8n8.x4.shared.b16 {%0,%1,%2,%3}, [%4];"
                 : "=r"(r[0]), "=r"(r[1]), "=r"(r[2]), "=r"(r[3]) : "r"(addr));
}
__device__ __forceinline__ void mma_bf16(float* c, const uint32_t* a,
                                         uint32_t b0, uint32_t b1) {
    asm volatile("mma.sync.aligned.m16n8k16.row.col.f32.bf16.bf16.f32 "
                 "{%0,%1,%2,%3}, {%4,%5,%6,%7}, {%8,%9}, {%0,%1,%2,%3};"
                 : "+f"(c[0]), "+f"(c[1]), "+f"(c[2]), "+f"(c[3])
                 : "r"(a[0]), "r"(a[1]), "r"(a[2]), "r"(a[3]), "r"(b0), "r"(b1));
}
__device__ __forceinline__ void cp16(uint32_t dst, const void* src) {
    asm volatile("cp.async.cg.shared.global [%0], [%1], 16;" :: "r"(dst), "l"(src));
}
#define CP_COMMIT() asm volatile("cp.async.commit_group;" ::: "memory")
#define CP_WAIT0()  asm volatile("cp.async.wait_group 0;" ::: "memory")

__device__ __forceinline__ void split2(float a, __nv_bfloat16& h, __nv_bfloat16& l) {
    h = __float2bfloat16(a);
    l = __float2bfloat16(a - __bfloat162float(h));
}

// ---------------------------------------------------------------------------
// bf16-split HMMA GEMM:  C[M,N] = scale * (A[M,K] * B[N,K]^T) (+bias, relu)
// A,B given as (hi,lo) bf16 split pairs, K-major row-major.
// Output: fp32 (Cf) OR bf16 split pair (Ch, Cl).
// Tile 128x128, BK=32, 2-stage cp.async pipeline, 8 warps (4M x 2N).
// smem rows padded to 80B: (row*80/16)%8 = (row*5)%8 is a permutation of 0..7
// -> conflict-free ldmatrix phases.
// ---------------------------------------------------------------------------
#define ROWB   80
#define TILEB  (128 * ROWB)      // 10240 B per operand tile
#define STAGEB (4 * TILEB)       // Ah, Al, Bh, Bl
#define GEMM_DSMEM (2 * STAGEB)  // 81920 B

__device__ __forceinline__ void issue_stage(uint32_t stAddr,
    const __nv_bfloat16* Ah, const __nv_bfloat16* Al,
    const __nv_bfloat16* Bh, const __nv_bfloat16* Bl,
    int lda, int ldb, int k0, int t)
{
    const __nv_bfloat16* base[4] = { Ah, Al, Bh, Bl };
    #pragma unroll
    for (int i = 0; i < 8; i++) {
        const int j    = t + i * 256;        // 2048 x 16B transfers
        const int tile = j >> 9;
        const int rem  = j & 511;
        const int row  = rem >> 2;
        const int ch   = rem & 3;
        const int ld   = (tile < 2) ? lda : ldb;
        const __nv_bfloat16* src = base[tile] + (size_t)row * ld + k0 + ch * 8;
        cp16(stAddr + tile * TILEB + row * ROWB + ch * 16, src);
    }
}

__global__ __launch_bounds__(256)
void gemm_bs(const __nv_bfloat16* __restrict__ Ah, const __nv_bfloat16* __restrict__ Al,
             const __nv_bfloat16* __restrict__ Bh, const __nv_bfloat16* __restrict__ Bl,
             const float* __restrict__ bias,
             float* __restrict__ Cf,
             __nv_bfloat16* __restrict__ Ch, __nv_bfloat16* __restrict__ Cl,
             int M, int N, int K,
             size_t sA, size_t sB, size_t sC,
             float scale, int relu)
{
    extern __shared__ char smem[];
    const uint32_t sb = smem_to_u32(smem);

    const int t    = threadIdx.x;
    const int wid  = t >> 5;
    const int lane = t & 31;
    const int wm   = wid >> 1;          // 0..3 -> M
    const int wn   = wid & 1;           // 0..1 -> N

    const int z = blockIdx.z;
    const int rowBase = blockIdx.y * 128;
    const int colBase = blockIdx.x * 128;
    const int lda = K, ldb = K;

    const __nv_bfloat16* pAh = Ah + (size_t)z * sA + (size_t)rowBase * lda;
    const __nv_bfloat16* pAl = Al + (size_t)z * sA + (size_t)rowBase * lda;
    const __nv_bfloat16* pBh = Bh + (size_t)z * sB + (size_t)colBase * ldb;
    const __nv_bfloat16* pBl = Bl + (size_t)z * sB + (size_t)colBase * ldb;

    float acc[2][8][4];
    #pragma unroll
    for (int mi = 0; mi < 2; mi++)
        #pragma unroll
        for (int ni = 0; ni < 8; ni++)
            #pragma unroll
            for (int r = 0; r < 4; r++) acc[mi][ni][r] = 0.0f;

    const int nc = K / 32;

    issue_stage(sb, pAh, pAl, pBh, pBl, lda, ldb, 0, t);
    CP_COMMIT();

    // per-thread ldmatrix source geometry
    const int lrow = (lane & 7) + ((lane >> 3) & 1) * 8;   // 0..15
    const uint32_t cSel = ((lane >> 4) & 1) * 16;          // 16B chunk select

    for (int c = 0; c < nc; c++) {
        const int s = c & 1;
        CP_WAIT0();
        __syncthreads();
        if (c + 1 < nc) {
            issue_stage(sb + (s ^ 1) * STAGEB, pAh, pAl, pBh, pBl,
                        lda, ldb, (c + 1) * 32, t);
            CP_COMMIT();
        }

        const uint32_t st = sb + s * STAGEB;
        #pragma unroll
        for (int ks = 0; ks < 2; ks++) {
            const uint32_t cb = ks * 32 + cSel;
            uint32_t ah[2][4], al[2][4];
            #pragma unroll
            for (int mi = 0; mi < 2; mi++) {
                const uint32_t ra = (uint32_t)(wm * 32 + mi * 16 + lrow) * ROWB + cb;
                ldsm4(ah[mi], st + ra);
                ldsm4(al[mi], st + TILEB + ra);
            }
            uint32_t bh[8][2], bl[8][2];
            #pragma unroll
            for (int g = 0; g < 4; g++) {
                const uint32_t rb = (uint32_t)(wn * 64 + g * 16 + lrow) * ROWB + cb;
                uint32_t q[4];
                ldsm4(q, st + 2 * TILEB + rb);
                bh[2*g][0] = q[0]; bh[2*g][1] = q[2];
                bh[2*g+1][0] = q[1]; bh[2*g+1][1] = q[3];
                ldsm4(q, st + 3 * TILEB + rb);
                bl[2*g][0] = q[0]; bl[2*g][1] = q[2];
                bl[2*g+1][0] = q[1]; bl[2*g+1][1] = q[3];
            }
            #pragma unroll
            for (int mi = 0; mi < 2; mi++)
                #pragma unroll
                for (int ni = 0; ni < 8; ni++) {
                    mma_bf16(acc[mi][ni], ah[mi], bh[ni][0], bh[ni][1]);
                    mma_bf16(acc[mi][ni], ah[mi], bl[ni][0], bl[ni][1]);
                    mma_bf16(acc[mi][ni], al[mi], bh[ni][0], bh[ni][1]);
                }
        }
        __syncthreads();
    }

    // ------------------------------ epilogue -------------------------------
    const int r0 = rowBase + wm * 32 + (lane >> 2);
    const int c0base = colBase + wn * 64 + (lane & 3) * 2;

    #pragma unroll
    for (int mi = 0; mi < 2; mi++) {
        #pragma unroll
        for (int rr = 0; rr < 2; rr++) {
            const int r = r0 + mi * 16 + rr * 8;
            #pragma unroll
            for (int ni = 0; ni < 8; ni++) {
                const int cc = c0base + ni * 8;
                float a = acc[mi][ni][rr * 2 + 0] * scale;
                float b = acc[mi][ni][rr * 2 + 1] * scale;
                if (bias) { a += bias[cc]; b += bias[cc + 1]; }
                if (relu) { a = fmaxf(a, 0.0f); b = fmaxf(b, 0.0f); }
                if (Cf) {
                    float2 v = make_float2(a, b);
                    *(float2*)(Cf + (size_t)z * sC + (size_t)r * N + cc) = v;
                } else {
                    __nv_bfloat16 hA, lA, hB, lB;
                    split2(a, hA, lA); split2(b, hB, lB);
                    *(__nv_bfloat162*)(Ch + (size_t)z * sC + (size_t)r * N + cc) =
                        __halves2bfloat162(hA, hB);
                    *(__nv_bfloat162*)(Cl + (size_t)z * sC + (size_t)r * N + cc) =
                        __halves2bfloat162(lA, lB);
                }
            }
        }
    }
}

// ---------------------------------------------------------------------------
// fp32 -> bf16 hi/lo elementwise split (for x)
// ---------------------------------------------------------------------------
__global__ __launch_bounds__(256)
void split_f32(const float* __restrict__ in, __nv_bfloat16* __restrict__ oh,
               __nv_bfloat16* __restrict__ ol, size_t n4)
{
    size_t i = (size_t)blockIdx.x * blockDim.x + threadIdx.x;
    if (i >= n4) return;
    float4 v = ((const float4*)in)[i];
    __nv_bfloat16 h0,l0,h1,l1,h2,l2,h3,l3;
    split2(v.x,h0,l0); split2(v.y,h1,l1); split2(v.z,h2,l2); split2(v.w,h3,l3);
    ((__nv_bfloat162*)oh)[2*i]   = __halves2bfloat162(h0,h1);
    ((__nv_bfloat162*)oh)[2*i+1] = __halves2bfloat162(h2,h3);
    ((__nv_bfloat162*)ol)[2*i]   = __halves2bfloat162(l0,l1);
    ((__nv_bfloat162*)ol)[2*i+1] = __halves2bfloat162(l2,l3);
}

// ---------------------------------------------------------------------------
// transpose + split: in fp32 [R,C] -> out bf16 hi/lo [C,R]   (z-batched)
// ---------------------------------------------------------------------------
__global__ __launch_bounds__(256)
void transpose_split(const float* __restrict__ in, __nv_bfloat16* __restrict__ oh,
                     __nv_bfloat16* __restrict__ ol, int R, int C,
                     size_t sIn, size_t sOut)
{
    __shared__ float tile[32][33];
    const int z = blockIdx.z;
    in += (size_t)z * sIn;  oh += (size_t)z * sOut;  ol += (size_t)z * sOut;
    const int c0 = blockIdx.x * 32, r0 = blockIdx.y * 32;
    const int tx = threadIdx.x & 31, ty = threadIdx.x >> 5;
    #pragma unroll
    for (int i = 0; i < 4; i++)
        tile[ty + i * 8][tx] = in[(size_t)(r0 + ty + i * 8) * C + c0 + tx];
    __syncthreads();
    #pragma unroll
    for (int i = 0; i < 4; i++) {
        const int ro = c0 + ty + i * 8;
        float v = tile[tx][ty + i * 8];
        __nv_bfloat16 h, l; split2(v, h, l);
        oh[(size_t)ro * R + r0 + tx] = h;
        ol[(size_t)ro * R + r0 + tx] = l;
    }
}

// ---------------------------------------------------------------------------
// Row softmax over 2048 cols; reads fp32 S, writes bf16 hi/lo splits of P.
// ---------------------------------------------------------------------------
__global__ __launch_bounds__(256)
void softmax_split(const float* __restrict__ S, __nv_bfloat16* __restrict__ Ph,
                   __nv_bfloat16* __restrict__ Pl)
{
    const size_t rowOff = (size_t)blockIdx.x * SEQ;
    const float* row = S + rowOff;
    const int t = threadIdx.x;
    __shared__ float red[256];

    float vals[8];
    *(float4*)&vals[0] = *(const float4*)&row[t * 8];
    *(float4*)&vals[4] = *(const float4*)&row[t * 8 + 4];

    float vmax = vals[0];
    #pragma unroll
    for (int i = 1; i < 8; i++) vmax = fmaxf(vmax, vals[i]);
    red[t] = vmax; __syncthreads();
    #pragma unroll
    for (int s = 128; s > 0; s >>= 1) { if (t < s) red[t] = fmaxf(red[t], red[t + s]); __syncthreads(); }
    const float m = red[0]; __syncthreads();

    float sum = 0.f;
    #pragma unroll
    for (int i = 0; i < 8; i++) { vals[i] = expf(vals[i] - m); sum += vals[i]; }
    red[t] = sum; __syncthreads();
    #pragma unroll
    for (int s = 128; s > 0; s >>= 1) { if (t < s) red[t] += red[t + s]; __syncthreads(); }
    const float inv = 1.0f / red[0];

    __nv_bfloat16* ph = Ph + rowOff + t * 8;
    __nv_bfloat16* pl = Pl + rowOff + t * 8;
    #pragma unroll
    for (int i = 0; i < 8; i += 2) {
        float a = vals[i] * inv, b = vals[i + 1] * inv;
        __nv_bfloat16 ah, al, bh, bl;
        split2(a, ah, al); split2(b, bh, bl);
        *(__nv_bfloat162*)(ph + i) = __halves2bfloat162(ah, bh);
        *(__nv_bfloat162*)(pl + i) = __halves2bfloat162(al, bl);
    }
}

// ---------------------------------------------------------------------------
extern "C" void kernel_launch(void* const* d_in, const int* in_sizes, int n_in,
                              void* d_out, int out_size)
{
    const float* x  = (const float*)d_in[0];
    const float* Wq = (const float*)d_in[1];
    const float* bq = (const float*)d_in[2];
    const float* Wk = (const float*)d_in[3];
    const float* bk = (const float*)d_in[4];
    const float* Wv = (const float*)d_in[5];
    const float* bv = (const float*)d_in[6];
    float* out = (float*)d_out;

    static int smemSet = 0;
    if (!smemSet) {
        cudaFuncSetAttribute(gemm_bs, cudaFuncAttributeMaxDynamicSharedMemorySize, GEMM_DSMEM);
        smemSet = 1;
    }

    __nv_bfloat16 *xh, *xl, *wqh, *wql, *wkh, *wkl, *wvh, *wvl;
    __nv_bfloat16 *qh, *ql, *kh, *kl, *vth, *vtl, *prh, *prl;
    float *V, *S;
    cudaGetSymbolAddress((void**)&xh,  g_xh);   cudaGetSymbolAddress((void**)&xl,  g_xl);
    cudaGetSymbolAddress((void**)&wqh, g_Wqt_h);cudaGetSymbolAddress((void**)&wql, g_Wqt_l);
    cudaGetSymbolAddress((void**)&wkh, g_Wkt_h);cudaGetSymbolAddress((void**)&wkl, g_Wkt_l);
    cudaGetSymbolAddress((void**)&wvh, g_Wvt_h);cudaGetSymbolAddress((void**)&wvl, g_Wvt_l);
    cudaGetSymbolAddress((void**)&qh,  g_Qh);   cudaGetSymbolAddress((void**)&ql,  g_Ql);
    cudaGetSymbolAddress((void**)&kh,  g_Kh);   cudaGetSymbolAddress((void**)&kl,  g_Kl);
    cudaGetSymbolAddress((void**)&V,   g_V);
    cudaGetSymbolAddress((void**)&vth, g_Vth);  cudaGetSymbolAddress((void**)&vtl, g_Vtl);
    cudaGetSymbolAddress((void**)&S,   g_S);
    cudaGetSymbolAddress((void**)&prh, g_Ph);   cudaGetSymbolAddress((void**)&prl, g_Pl);

    // 1) split x -> bf16 hi/lo
    {
        size_t n4 = (size_t)MTOT * DIM / 4;
        split_f32<<<(unsigned)((n4 + 255) / 256), 256>>>(x, xh, xl, n4);
    }
    // 2) transpose+split weights: W[D, E] -> Wt[E, D]
    {
        dim3 g(DIM / 32, DIM / 32, 1);
        transpose_split<<<g, 256>>>(Wq, wqh, wql, DIM, DIM, 0, 0);
        transpose_split<<<g, 256>>>(Wk, wkh, wkl, DIM, DIM, 0, 0);
        transpose_split<<<g, 256>>>(Wv, wvh, wvl, DIM, DIM, 0, 0);
    }
    // 3) projections: Q,K -> bf16 splits; V -> fp32 (for transpose)
    {
        dim3 g(DIM / 128, MTOT / 128, 1);
        gemm_bs<<<g, 256, GEMM_DSMEM>>>(xh, xl, wqh, wql, bq, nullptr, qh, ql,
                                        MTOT, DIM, DIM, 0, 0, 0, 1.0f, 1);
        gemm_bs<<<g, 256, GEMM_DSMEM>>>(xh, xl, wkh, wkl, bk, nullptr, kh, kl,
                                        MTOT, DIM, DIM, 0, 0, 0, 1.0f, 1);
        gemm_bs<<<g, 256, GEMM_DSMEM>>>(xh, xl, wvh, wvl, bv, V, nullptr, nullptr,
                                        MTOT, DIM, DIM, 0, 0, 0, 1.0f, 1);
    }
    // 4) transpose+split V per batch: [SEQ, DIM] -> [DIM, SEQ]
    {
        dim3 g(DIM / 32, SEQ / 32, BATCH);
        transpose_split<<<g, 256>>>(V, vth, vtl, SEQ, DIM,
                                    (size_t)SEQ * DIM, (size_t)DIM * SEQ);
    }
    // 5) scores = scale * Q K^T per batch (fp32 out)
    {
        const float scale = 1.0f / sqrtf((float)DIM);
        dim3 g(SEQ / 128, SEQ / 128, BATCH);
        gemm_bs<<<g, 256, GEMM_DSMEM>>>(qh, ql, kh, kl, nullptr, S, nullptr, nullptr,
                                        SEQ, SEQ, DIM,
                                        (size_t)SEQ * DIM, (size_t)SEQ * DIM,
                                        (size_t)SEQ * SEQ, scale, 0);
    }
    // 6) softmax -> P bf16 splits
    softmax_split<<<BATCH * SEQ, 256>>>(S, prh, prl);

    // 7) out = P V per batch (fp32 out): A = P [SEQ, SEQ], B = Vt [DIM, SEQ]
    {
        dim3 g(DIM / 128, SEQ / 128, BATCH);
        gemm_bs<<<g, 256, GEMM_DSMEM>>>(prh, prl, vth, vtl, nullptr, out, nullptr, nullptr,
                                        SEQ, DIM, SEQ,
                                        (size_t)SEQ * SEQ, (size_t)DIM * SEQ,
                                        (size_t)SEQ * DIM, 1.0f, 0);
    }
}